// round 5
// baseline (speedup 1.0000x reference)
#include <cuda_runtime.h>
#include <math.h>

#define T_LEN 8192
#define E_DIM 1024
#define D_DIM 1028
#define NTAG  50

// Scratch (static __device__ globals: allocation-free per harness rules)
__device__ float g_A[T_LEN * 16];   // per-step gate angles (bias + theta folded in)
__device__ float g_H[T_LEN * 4];    // per-step hidden state

__device__ __forceinline__ float tanh_ap(float x) {
    float y;
    asm("tanh.approx.f32 %0, %1;" : "=f"(y) : "f"(x));
    return y;
}

// ---------------------------------------------------------------------------
// Kernel 1: A[t, g*4+w] = b_g[w] + th_g[w] + sum_e emb[sent[t],e] * W_g[w,e]
// Block: 512 threads = 16 warps = 16 outputs; 8 tokens per block.
// ---------------------------------------------------------------------------
__global__ __launch_bounds__(512) void k_pre(
    const int*   __restrict__ sent, const float* __restrict__ emb,
    const float* __restrict__ Wf,  const float* __restrict__ bf,
    const float* __restrict__ Wi,  const float* __restrict__ bi,
    const float* __restrict__ Wu,  const float* __restrict__ bu,
    const float* __restrict__ Wo,  const float* __restrict__ bo,
    const float* __restrict__ thf, const float* __restrict__ thi,
    const float* __restrict__ thu, const float* __restrict__ tho)
{
    const int warp = threadIdx.x >> 5;          // 0..15  -> output index
    const int lane = threadIdx.x & 31;
    const int tokg = blockIdx.x;                // token group (8 tokens)
    const int out  = warp;
    const int g    = out >> 2, w = out & 3;

    const float* Wg = (g == 0) ? Wf : (g == 1) ? Wi : (g == 2) ? Wu : Wo;
    const float* bg = (g == 0) ? bf : (g == 1) ? bi : (g == 2) ? bu : bo;
    const float* tg = (g == 0) ? thf : (g == 1) ? thi : (g == 2) ? thu : tho;

    const float4* wrow = (const float4*)(Wg + w * D_DIM);

    const float4* xrow[8];
    #pragma unroll
    for (int tk = 0; tk < 8; tk++) {
        int tok = tokg * 8 + tk;
        xrow[tk] = (const float4*)(emb + (size_t)__ldg(sent + tok) * E_DIM);
    }

    float acc[8];
    #pragma unroll
    for (int tk = 0; tk < 8; tk++) acc[tk] = 0.f;

    #pragma unroll
    for (int j = 0; j < 8; j++) {
        int e4 = j * 32 + lane;
        float4 wv = __ldg(wrow + e4);
        #pragma unroll
        for (int tk = 0; tk < 8; tk++) {
            float4 xv = __ldg(xrow[tk] + e4);
            acc[tk] = fmaf(xv.x, wv.x, acc[tk]);
            acc[tk] = fmaf(xv.y, wv.y, acc[tk]);
            acc[tk] = fmaf(xv.z, wv.z, acc[tk]);
            acc[tk] = fmaf(xv.w, wv.w, acc[tk]);
        }
    }

    #pragma unroll
    for (int tk = 0; tk < 8; tk++) {
        float v = acc[tk];
        #pragma unroll
        for (int off = 16; off; off >>= 1)
            v += __shfl_xor_sync(0xffffffffu, v, off);
        acc[tk] = v;
    }

    if (lane == 0) {
        float add = __ldg(bg + w) + __ldg(tg + w);
        #pragma unroll
        for (int tk = 0; tk < 8; tk++) {
            int tok = tokg * 8 + tk;
            g_A[tok * 16 + out] = acc[tk] + add;
        }
    }
}

// ---------------------------------------------------------------------------
// Kernel 2: serial LSTM scan, 7 shuffles/step.
// Lane layout: lid = lane & 15 = g*4 + w; lanes 16-31 mirror 0-15.
//  - cosine products: s1 = xor1(C), pp = C*s1, s2 = xor2(pp)
//       y0=s1*s2  y1=pp  y2=s2*C  y3=s2*pp      (2 SHFL)
//  - act allgather across gates: xor4, xor8, xor8-of-xor4 + SEL rotation
//       -> each lane computes its wire's c, h locally (3 SHFL)
//  - h distribution via peer-weight partial dot:
//       x1 = xor1(h); pSelf/pPeer partial dots; x2 = xor2(pPeer);
//       delta = pSelf + x2                       (2 SHFL)
// ---------------------------------------------------------------------------
__global__ __launch_bounds__(32) void k_scan(
    const float* __restrict__ Wf, const float* __restrict__ Wi,
    const float* __restrict__ Wu, const float* __restrict__ Wo)
{
    const unsigned M = 0xFFFFFFFFu;
    const int lane = threadIdx.x & 31;
    const int lid  = lane & 15;
    const int w    = lid & 3;
    const int g    = lid >> 2;

    const float* Wg = (g == 0) ? Wf : (g == 1) ? Wi : (g == 2) ? Wu : Wo;
    // own-row recurrent weights at wire indices {w, w^1}
    const float whA  = Wg[w       * D_DIM + E_DIM + w];
    const float whB  = Wg[w       * D_DIM + E_DIM + (w ^ 1)];
    // xor2-peer row's weights at the SAME wire indices {w, w^1}
    const float whPA = Wg[(w ^ 2) * D_DIM + E_DIM + w];
    const float whPB = Wg[(w ^ 2) * D_DIM + E_DIM + (w ^ 1)];

    // activation: sigmoid = 0.5 + 0.5*tanh(0.5*y); tanh gate (g==2) direct
    const float A1 = (g == 2) ? 1.0f : 0.5f;
    const float A0 = (g == 2) ? 0.0f : 0.5f;
    const float K  = (g == 2) ? 1.0f : 0.5f;

    float c = 0.f;          // cell state for own wire
    float delta = 0.f;      // wh . h  (recurrent contribution to pre)

    const float* Ap = g_A + lid;

    // prefetch pipeline (depth 4); A sits in L2
    float b0 = __ldg(Ap + 0 * 16);
    float b1 = __ldg(Ap + 1 * 16);
    float b2 = __ldg(Ap + 2 * 16);
    float b3 = __ldg(Ap + 3 * 16);

#define SCAN_STEP(TT, ABUF)                                                    \
    do {                                                                       \
        float pre = ABUF + delta;                                              \
        float C   = __cosf(pre);                                               \
        float s1  = __shfl_xor_sync(M, C, 1);                                  \
        float pp  = C * s1;                                                    \
        float s2  = __shfl_xor_sync(M, pp, 2);                                 \
        float y = (w == 0) ? s1 * s2 : (w == 1) ? pp                           \
                : (w == 2) ? s2 * C  : s2 * pp;                                \
        float act = fmaf(A1, tanh_ap(K * y), A0);                              \
        float s4  = __shfl_xor_sync(M, act, 4);                                \
        float s8  = __shfl_xor_sync(M, act, 8);                                \
        float s84 = __shfl_xor_sync(M, s4, 8);                                 \
        float fv = (g == 0) ? act : (g == 1) ? s4  : (g == 2) ? s8  : s84;     \
        float iv = (g == 0) ? s4  : (g == 1) ? act : (g == 2) ? s84 : s8;      \
        float uv = (g == 0) ? s8  : (g == 1) ? s84 : (g == 2) ? act : s4;      \
        float ov = (g == 0) ? s84 : (g == 1) ? s8  : (g == 2) ? s4  : act;     \
        c = fmaf(fv, c, iv * uv);                                              \
        float h = ov * tanh_ap(c);                                             \
        g_H[(TT) * 4 + w] = h; /* multi-writer, identical value */             \
        float x1 = __shfl_xor_sync(M, h, 1);                                   \
        float pSelf = fmaf(whA,  h, whB  * x1);                                \
        float pPeer = fmaf(whPA, h, whPB * x1);                                \
        float x2 = __shfl_xor_sync(M, pPeer, 2);                               \
        delta = pSelf + x2;                                                    \
        ABUF = __ldg(Ap + (size_t)(((TT) + 4) & (T_LEN - 1)) * 16);            \
    } while (0)

    for (int tb = 0; tb < T_LEN; tb += 4) {
        SCAN_STEP(tb + 0, b0);
        SCAN_STEP(tb + 1, b1);
        SCAN_STEP(tb + 2, b2);
        SCAN_STEP(tb + 3, b3);
    }
#undef SCAN_STEP
}

// ---------------------------------------------------------------------------
// Kernel 3: tag logits + log_softmax. One warp per token.
// ---------------------------------------------------------------------------
__global__ __launch_bounds__(256) void k_out(
    const float* __restrict__ Wt, const float* __restrict__ bt,
    float* __restrict__ outp)
{
    const int gwarp = (blockIdx.x * blockDim.x + threadIdx.x) >> 5;
    const int lane  = threadIdx.x & 31;
    if (gwarp >= T_LEN) return;

    const float4 h = *(const float4*)(g_H + gwarp * 4);

    float l0;
    {
        const float4 wr = *(const float4*)(Wt + lane * 4);
        l0 = __ldg(bt + lane);
        l0 = fmaf(h.x, wr.x, l0);
        l0 = fmaf(h.y, wr.y, l0);
        l0 = fmaf(h.z, wr.z, l0);
        l0 = fmaf(h.w, wr.w, l0);
    }
    const bool v1 = (lane + 32) < NTAG;
    float l1 = __int_as_float(0xff800000);  // -inf
    if (v1) {
        const float4 wr = *(const float4*)(Wt + (lane + 32) * 4);
        l1 = __ldg(bt + lane + 32);
        l1 = fmaf(h.x, wr.x, l1);
        l1 = fmaf(h.y, wr.y, l1);
        l1 = fmaf(h.z, wr.z, l1);
        l1 = fmaf(h.w, wr.w, l1);
    }

    float m = fmaxf(l0, l1);
    #pragma unroll
    for (int off = 16; off; off >>= 1)
        m = fmaxf(m, __shfl_xor_sync(0xffffffffu, m, off));

    float s = expf(l0 - m) + (v1 ? expf(l1 - m) : 0.f);
    #pragma unroll
    for (int off = 16; off; off >>= 1)
        s += __shfl_xor_sync(0xffffffffu, s, off);

    const float lse = m + logf(s);

    outp[gwarp * NTAG + lane] = l0 - lse;
    if (v1) outp[gwarp * NTAG + lane + 32] = l1 - lse;
}

// ---------------------------------------------------------------------------
extern "C" void kernel_launch(void* const* d_in, const int* in_sizes, int n_in,
                              void* d_out, int out_size)
{
    const int*   sent = (const int*)  d_in[0];
    const float* emb  = (const float*)d_in[1];
    const float* Wf   = (const float*)d_in[2];
    const float* bf   = (const float*)d_in[3];
    const float* Wi   = (const float*)d_in[4];
    const float* bi   = (const float*)d_in[5];
    const float* Wu   = (const float*)d_in[6];
    const float* bu   = (const float*)d_in[7];
    const float* Wo   = (const float*)d_in[8];
    const float* bo   = (const float*)d_in[9];
    const float* thf  = (const float*)d_in[10];
    const float* thi  = (const float*)d_in[11];
    const float* thu  = (const float*)d_in[12];
    const float* tho  = (const float*)d_in[13];
    const float* Wt   = (const float*)d_in[14];
    const float* bt   = (const float*)d_in[15];
    float* outp = (float*)d_out;

    k_pre<<<T_LEN / 8, 512>>>(sent, emb, Wf, bf, Wi, bi, Wu, bu, Wo, bo,
                              thf, thi, thu, tho);
    k_scan<<<1, 32>>>(Wf, Wi, Wu, Wo);
    k_out<<<T_LEN / 8, 256>>>(Wt, bt, outp);
}

// round 6
// speedup vs baseline: 1.0603x; 1.0603x over previous
#include <cuda_runtime.h>
#include <math.h>

#define T_LEN 8192
#define E_DIM 1024
#define D_DIM 1028
#define NTAG  50

// Scratch (static __device__ globals: allocation-free per harness rules)
// g_A layout: [t][w][g]  (w-major so one lane reads its wire's 4 gates as float4)
__device__ float g_A[T_LEN * 16];
__device__ float g_H[T_LEN * 4];

__device__ __forceinline__ float tanh_ap(float x) {
    float y;
    asm("tanh.approx.f32 %0, %1;" : "=f"(y) : "f"(x));
    return y;
}

__device__ __forceinline__ unsigned smem_u32(const void* p) {
    unsigned a;
    asm("{ .reg .u64 t; cvta.to.shared.u64 t, %1; cvt.u32.u64 %0, t; }"
        : "=r"(a) : "l"(p));
    return a;
}
__device__ __forceinline__ void sts1(unsigned addr, float v) {
    asm volatile("st.shared.f32 [%0], %1;" :: "r"(addr), "f"(v));
}
__device__ __forceinline__ float4 lds4(unsigned addr) {
    float4 r;
    asm volatile("ld.shared.v4.f32 {%0,%1,%2,%3}, [%4];"
                 : "=f"(r.x), "=f"(r.y), "=f"(r.z), "=f"(r.w) : "r"(addr));
    return r;
}

// ---------------------------------------------------------------------------
// Kernel 1: A[t][w][g] = b_g[w] + th_g[w] + sum_e emb[sent[t],e] * W_g[w,e]
// Block: 512 threads = 16 warps = 16 outputs; 8 tokens per block.
// ---------------------------------------------------------------------------
__global__ __launch_bounds__(512) void k_pre(
    const int*   __restrict__ sent, const float* __restrict__ emb,
    const float* __restrict__ Wf,  const float* __restrict__ bf,
    const float* __restrict__ Wi,  const float* __restrict__ bi,
    const float* __restrict__ Wu,  const float* __restrict__ bu,
    const float* __restrict__ Wo,  const float* __restrict__ bo,
    const float* __restrict__ thf, const float* __restrict__ thi,
    const float* __restrict__ thu, const float* __restrict__ tho)
{
    const int warp = threadIdx.x >> 5;          // 0..15  -> output index
    const int lane = threadIdx.x & 31;
    const int tokg = blockIdx.x;                // token group (8 tokens)
    const int out  = warp;
    const int g    = out >> 2, w = out & 3;

    const float* Wg = (g == 0) ? Wf : (g == 1) ? Wi : (g == 2) ? Wu : Wo;
    const float* bg = (g == 0) ? bf : (g == 1) ? bi : (g == 2) ? bu : bo;
    const float* tg = (g == 0) ? thf : (g == 1) ? thi : (g == 2) ? thu : tho;

    const float4* wrow = (const float4*)(Wg + w * D_DIM);

    const float4* xrow[8];
    #pragma unroll
    for (int tk = 0; tk < 8; tk++) {
        int tok = tokg * 8 + tk;
        xrow[tk] = (const float4*)(emb + (size_t)__ldg(sent + tok) * E_DIM);
    }

    float acc[8];
    #pragma unroll
    for (int tk = 0; tk < 8; tk++) acc[tk] = 0.f;

    #pragma unroll
    for (int j = 0; j < 8; j++) {
        int e4 = j * 32 + lane;
        float4 wv = __ldg(wrow + e4);
        #pragma unroll
        for (int tk = 0; tk < 8; tk++) {
            float4 xv = __ldg(xrow[tk] + e4);
            acc[tk] = fmaf(xv.x, wv.x, acc[tk]);
            acc[tk] = fmaf(xv.y, wv.y, acc[tk]);
            acc[tk] = fmaf(xv.z, wv.z, acc[tk]);
            acc[tk] = fmaf(xv.w, wv.w, acc[tk]);
        }
    }

    #pragma unroll
    for (int tk = 0; tk < 8; tk++) {
        float v = acc[tk];
        #pragma unroll
        for (int off = 16; off; off >>= 1)
            v += __shfl_xor_sync(0xffffffffu, v, off);
        acc[tk] = v;
    }

    if (lane == 0) {
        float add = __ldg(bg + w) + __ldg(tg + w);
        #pragma unroll
        for (int tk = 0; tk < 8; tk++) {
            int tok = tokg * 8 + tk;
            g_A[tok * 16 + w * 4 + g] = acc[tk] + add;   // w-major layout
        }
    }
}

// ---------------------------------------------------------------------------
// Kernel 2: serial LSTM scan — ZERO shuffles, ZERO syncwarps.
// Every lane handles wire w = lane&3 (8x redundant across the warp; all
// redundant lanes write identical values to identical addresses).
// Per step:
//   1. pre_g = A[t][w][g] + dot(wh_g, h)      (local, float4 h)
//   2. C_g = cos(pre_g); STS cbuf[g*4+w]      (4 scalar STS)
//   3. LDS.128 x4 -> all 16 cosines; y_g for own wire; acts f,i,u,o (local!)
//   4. c, h for own wire (local); STS hbuf[w]; LDS.128 -> h vector
// Same-warp STS->LDS coherence: single never-diverged warp, LSU processes
// shared ops in program order (asm volatile pins SASS order).
// ---------------------------------------------------------------------------
__global__ __launch_bounds__(32) void k_scan(
    const float* __restrict__ Wf, const float* __restrict__ Wi,
    const float* __restrict__ Wu, const float* __restrict__ Wo)
{
    __shared__ float cbuf[16];
    __shared__ float hbuf[4];

    const int lane = threadIdx.x & 31;
    const int w    = lane & 3;

    const unsigned cb_a = smem_u32(cbuf);
    const unsigned hb_a = smem_u32(hbuf);

    // recurrent weights: row w, columns E..E+3 of each gate matrix
    const float4 whF = *(const float4*)(Wf + w * D_DIM + E_DIM);
    const float4 whI = *(const float4*)(Wi + w * D_DIM + E_DIM);
    const float4 whU = *(const float4*)(Wu + w * D_DIM + E_DIM);
    const float4 whO = *(const float4*)(Wo + w * D_DIM + E_DIM);

    float  c  = 0.f;
    float4 hv = make_float4(0.f, 0.f, 0.f, 0.f);

    // A as float4 per (t, w): element index t*4 + w
    const float4* Ap = (const float4*)g_A;

    float4 a0 = __ldg(Ap + 0 * 4 + w);
    float4 a1 = __ldg(Ap + 1 * 4 + w);
    float4 a2 = __ldg(Ap + 2 * 4 + w);
    float4 a3 = __ldg(Ap + 3 * 4 + w);

#define DOT4(WH, A0)                                                           \
    fmaf((WH).w, hv.w, fmaf((WH).z, hv.z, fmaf((WH).y, hv.y,                   \
         fmaf((WH).x, hv.x, (A0)))))

#define YW(C)                                                                  \
    ((w == 0) ? (C).y * ((C).z * (C).w)                                        \
   : (w == 1) ? (C).x * (C).y                                                  \
   : (w == 2) ? ((C).x * (C).y) * (C).z                                        \
              : ((C).x * (C).y) * ((C).z * (C).w))

#define SCAN_STEP(TT, AV)                                                      \
    do {                                                                       \
        float pf = DOT4(whF, (AV).x);                                          \
        float pi = DOT4(whI, (AV).y);                                          \
        float pu = DOT4(whU, (AV).z);                                          \
        float po = DOT4(whO, (AV).w);                                          \
        sts1(cb_a + (0  + w) * 4, __cosf(pf));                                 \
        sts1(cb_a + (4  + w) * 4, __cosf(pi));                                 \
        sts1(cb_a + (8  + w) * 4, __cosf(pu));                                 \
        sts1(cb_a + (12 + w) * 4, __cosf(po));                                 \
        float4 CF = lds4(cb_a + 0);                                            \
        float4 CI = lds4(cb_a + 16);                                           \
        float4 CU = lds4(cb_a + 32);                                           \
        float4 CO = lds4(cb_a + 48);                                           \
        float fv = fmaf(0.5f, tanh_ap(0.5f * YW(CF)), 0.5f);                   \
        float iv = fmaf(0.5f, tanh_ap(0.5f * YW(CI)), 0.5f);                   \
        float uv = tanh_ap(YW(CU));                                            \
        float ov = fmaf(0.5f, tanh_ap(0.5f * YW(CO)), 0.5f);                   \
        c = fmaf(fv, c, iv * uv);                                              \
        float hn = ov * tanh_ap(c);                                            \
        g_H[(TT) * 4 + w] = hn;   /* multi-writer, identical value */          \
        sts1(hb_a + w * 4, hn);                                                \
        hv = lds4(hb_a);                                                       \
        AV = __ldg(Ap + (size_t)((((TT) + 4) & (T_LEN - 1)) * 4 + w));         \
    } while (0)

    for (int tb = 0; tb < T_LEN; tb += 4) {
        SCAN_STEP(tb + 0, a0);
        SCAN_STEP(tb + 1, a1);
        SCAN_STEP(tb + 2, a2);
        SCAN_STEP(tb + 3, a3);
    }
#undef SCAN_STEP
#undef DOT4
#undef YW
}

// ---------------------------------------------------------------------------
// Kernel 3: tag logits + log_softmax. One warp per token.
// ---------------------------------------------------------------------------
__global__ __launch_bounds__(256) void k_out(
    const float* __restrict__ Wt, const float* __restrict__ bt,
    float* __restrict__ outp)
{
    const int gwarp = (blockIdx.x * blockDim.x + threadIdx.x) >> 5;
    const int lane  = threadIdx.x & 31;
    if (gwarp >= T_LEN) return;

    const float4 h = *(const float4*)(g_H + gwarp * 4);

    float l0;
    {
        const float4 wr = *(const float4*)(Wt + lane * 4);
        l0 = __ldg(bt + lane);
        l0 = fmaf(h.x, wr.x, l0);
        l0 = fmaf(h.y, wr.y, l0);
        l0 = fmaf(h.z, wr.z, l0);
        l0 = fmaf(h.w, wr.w, l0);
    }
    const bool v1 = (lane + 32) < NTAG;
    float l1 = __int_as_float(0xff800000);  // -inf
    if (v1) {
        const float4 wr = *(const float4*)(Wt + (lane + 32) * 4);
        l1 = __ldg(bt + lane + 32);
        l1 = fmaf(h.x, wr.x, l1);
        l1 = fmaf(h.y, wr.y, l1);
        l1 = fmaf(h.z, wr.z, l1);
        l1 = fmaf(h.w, wr.w, l1);
    }

    float m = fmaxf(l0, l1);
    #pragma unroll
    for (int off = 16; off; off >>= 1)
        m = fmaxf(m, __shfl_xor_sync(0xffffffffu, m, off));

    float s = expf(l0 - m) + (v1 ? expf(l1 - m) : 0.f);
    #pragma unroll
    for (int off = 16; off; off >>= 1)
        s += __shfl_xor_sync(0xffffffffu, s, off);

    const float lse = m + logf(s);

    outp[gwarp * NTAG + lane] = l0 - lse;
    if (v1) outp[gwarp * NTAG + lane + 32] = l1 - lse;
}

// ---------------------------------------------------------------------------
extern "C" void kernel_launch(void* const* d_in, const int* in_sizes, int n_in,
                              void* d_out, int out_size)
{
    const int*   sent = (const int*)  d_in[0];
    const float* emb  = (const float*)d_in[1];
    const float* Wf   = (const float*)d_in[2];
    const float* bf   = (const float*)d_in[3];
    const float* Wi   = (const float*)d_in[4];
    const float* bi   = (const float*)d_in[5];
    const float* Wu   = (const float*)d_in[6];
    const float* bu   = (const float*)d_in[7];
    const float* Wo   = (const float*)d_in[8];
    const float* bo   = (const float*)d_in[9];
    const float* thf  = (const float*)d_in[10];
    const float* thi  = (const float*)d_in[11];
    const float* thu  = (const float*)d_in[12];
    const float* tho  = (const float*)d_in[13];
    const float* Wt   = (const float*)d_in[14];
    const float* bt   = (const float*)d_in[15];
    float* outp = (float*)d_out;

    k_pre<<<T_LEN / 8, 512>>>(sent, emb, Wf, bf, Wi, bi, Wu, bu, Wo, bo,
                              thf, thi, thu, tho);
    k_scan<<<1, 32>>>(Wf, Wi, Wu, Wo);
    k_out<<<T_LEN / 8, 256>>>(Wt, bt, outp);
}